// round 2
// baseline (speedup 1.0000x reference)
#include <cuda_runtime.h>
#include <cuda_bf16.h>
#include <cstdint>

// Shapes fixed for this problem:
//   hidden_states [4,2048,1024] f32, input_ids [4,2048] (int32 or int64 — detected),
//   W1_w [1024,1024] f32, W1_b [1024] f32, W2_w [1024,1024] f32, W2_b [1024] f32, n (=3)
// out [4,2048,1024] f32 = X@W1^T + b1 + pooled@W2^T + b2
// pooled[b,q] = mean_{k<q, ngram(k)==ngram(q)} hidden[b,k]  (0 if no match)

static constexpr int BATCH = 4;
static constexpr int LSEQ  = 2048;
static constexpr int DDIM  = 1024;
static constexpr int MROWS = BATCH * LSEQ;   // 8192
static constexpr int NCOLS = DDIM;
static constexpr int KDIM  = DDIM;

// ---------------- device scratch (no allocations allowed) ----------------
__device__ unsigned long long g_codes[MROWS];
__device__ float g_pooled[(size_t)MROWS * DDIM];   // only matched rows touched
__device__ int g_wl[MROWS];
__device__ int g_wl_count;
__device__ int g_ids_is64;

// ---------------- kernel 0: detect ids dtype + reset worklist ----------------
// ids are in [0,64). If the buffer is int64, every odd 32-bit word is the high
// half of a small nonnegative value -> 0. If int32, odd words are ids and the
// probability all 4096 are zero is (1/64)^4096 ~ 0.
__global__ void detect_kernel(const unsigned int* __restrict__ w)
{
    __shared__ int s_any;
    if (threadIdx.x == 0) s_any = 0;
    __syncthreads();
    for (int i = 2 * threadIdx.x + 1; i < MROWS; i += 2 * blockDim.x)
        if (w[i] != 0u) s_any = 1;          // benign race
    __syncthreads();
    if (threadIdx.x == 0) {
        g_ids_is64 = (s_any == 0) ? 1 : 0;
        g_wl_count = 0;
    }
}

// ---------------- kernel 1: pack n-gram codes ----------------
__global__ void prep_codes_kernel(const void* __restrict__ ids_raw,
                                  const int* __restrict__ n_ptr)
{
    int idx = blockIdx.x * blockDim.x + threadIdx.x;
    if (idx >= MROWS) return;
    int n = *n_ptr;                          // value 3 in first word for i32 or i64
    int is64 = g_ids_is64;
    const int*       i32 = (const int*)ids_raw;
    const long long* i64 = (const long long*)ids_raw;
    int b = idx / LSEQ;
    int q = idx % LSEQ;
    unsigned long long code = 0ull;
    if (q >= n - 1) {
        for (int i = 0; i < n; i++) {
            int pos = b * LSEQ + (q - n + 1 + i);
            long long v = is64 ? i64[pos] : (long long)i32[pos];
            code = (code << 16) | (unsigned long long)(v & 0xFFFF);
        }
    }
    // q < n-1: reference pads with an all-zero tuple -> code 0 (consistent)
    g_codes[idx] = code;
}

// ---------------- kernel 2: find matches, build pooled rows + worklist ----------------
__global__ __launch_bounds__(256) void pool_kernel(const float* __restrict__ hidden)
{
    __shared__ int s_match[LSEQ];
    __shared__ int s_cnt;
    int blk = blockIdx.x;               // = b*LSEQ + q
    int tid = threadIdx.x;
    int b = blk / LSEQ;
    int q = blk % LSEQ;
    if (tid == 0) s_cnt = 0;
    __syncthreads();
    unsigned long long myc = g_codes[blk];
    for (int k = tid; k < q; k += 256) {           // strict causal: k < q
        if (g_codes[b * LSEQ + k] == myc) {
            int pos = atomicAdd(&s_cnt, 1);
            s_match[pos] = k;
        }
    }
    __syncthreads();
    int cnt = s_cnt;
    if (cnt == 0) return;
    if (tid == 0) {
        int wi = atomicAdd(&g_wl_count, 1);
        g_wl[wi] = blk;
    }
    int c = tid * 4;
    float4 acc = make_float4(0.f, 0.f, 0.f, 0.f);
    for (int m = 0; m < cnt; m++) {
        const float4 h = *(const float4*)&hidden[((size_t)b * LSEQ + s_match[m]) * DDIM + c];
        acc.x += h.x; acc.y += h.y; acc.z += h.z; acc.w += h.w;
    }
    float inv = 1.0f / (float)cnt;
    acc.x *= inv; acc.y *= inv; acc.z *= inv; acc.w *= inv;
    *(float4*)&g_pooled[(size_t)blk * DDIM + c] = acc;
}

// ---------------- kernel 3: main GEMM  out = X @ W1^T + (b1+b2) ----------------
static constexpr int BM = 128, BN = 128, BK = 16, TM = 8, TN = 8;

__global__ __launch_bounds__(256, 2)
void gemm_bias_kernel(const float* __restrict__ A,   // [MROWS, K]
                      const float* __restrict__ Bw,  // [NCOLS, K]
                      const float* __restrict__ b1,
                      const float* __restrict__ b2,
                      float* __restrict__ C)
{
    __shared__ float As[BK][BM + 4];
    __shared__ float Bs[BK][BN + 4];
    int tid  = threadIdx.x;
    int row0 = blockIdx.y * BM;
    int col0 = blockIdx.x * BN;
    int lr = tid / 4;              // 0..63
    int lk = (tid % 4) * 4;        // 0,4,8,12
    int tr = (tid / 16) * TM;
    int tc = (tid % 16) * TN;

    float acc[TM][TN];
#pragma unroll
    for (int i = 0; i < TM; i++)
#pragma unroll
        for (int j = 0; j < TN; j++) acc[i][j] = 0.f;

    for (int k0 = 0; k0 < KDIM; k0 += BK) {
#pragma unroll
        for (int p = 0; p < 2; p++) {
            int r = lr + p * 64;
            float4 va = *(const float4*)&A[(size_t)(row0 + r) * KDIM + k0 + lk];
            As[lk + 0][r] = va.x; As[lk + 1][r] = va.y;
            As[lk + 2][r] = va.z; As[lk + 3][r] = va.w;
            float4 vb = *(const float4*)&Bw[(size_t)(col0 + r) * KDIM + k0 + lk];
            Bs[lk + 0][r] = vb.x; Bs[lk + 1][r] = vb.y;
            Bs[lk + 2][r] = vb.z; Bs[lk + 3][r] = vb.w;
        }
        __syncthreads();
#pragma unroll
        for (int kk = 0; kk < BK; kk++) {
            float ra[TM], rb[TN];
#pragma unroll
            for (int i = 0; i < TM; i++) ra[i] = As[kk][tr + i];
#pragma unroll
            for (int j = 0; j < TN; j++) rb[j] = Bs[kk][tc + j];
#pragma unroll
            for (int i = 0; i < TM; i++)
#pragma unroll
                for (int j = 0; j < TN; j++)
                    acc[i][j] += ra[i] * rb[j];
        }
        __syncthreads();
    }

#pragma unroll
    for (int i = 0; i < TM; i++) {
        int r = row0 + tr + i;
#pragma unroll
        for (int j = 0; j < TN; j += 4) {
            int c = col0 + tc + j;
            float4 o;
            o.x = acc[i][j + 0] + b1[c + 0] + b2[c + 0];
            o.y = acc[i][j + 1] + b1[c + 1] + b2[c + 1];
            o.z = acc[i][j + 2] + b1[c + 2] + b2[c + 2];
            o.w = acc[i][j + 3] + b1[c + 3] + b2[c + 3];
            *(float4*)&C[(size_t)r * NCOLS + c] = o;
        }
    }
}

// ---------------- kernel 4: sparse fixup  out[row] += pooled[row] @ W2^T ----------------
__global__ __launch_bounds__(256) void fixup_kernel(const float* __restrict__ W2,
                                                    float* __restrict__ C)
{
    int slot = blockIdx.x;
    if (slot >= g_wl_count) return;
    int row = g_wl[slot];

    __shared__ float s_x[DDIM];
    int tid = threadIdx.x;
    for (int d = tid; d < DDIM; d += 256) s_x[d] = g_pooled[(size_t)row * DDIM + d];
    __syncthreads();

    int warp = tid / 32;
    int lane = tid % 32;
    for (int j = warp * 128; j < warp * 128 + 128; j++) {
        const float* wrow = &W2[(size_t)j * KDIM];
        float sum = 0.f;
        for (int d = lane; d < KDIM; d += 32) sum += s_x[d] * wrow[d];
#pragma unroll
        for (int off = 16; off > 0; off >>= 1)
            sum += __shfl_down_sync(0xFFFFFFFFu, sum, off);
        if (lane == 0) C[(size_t)row * NCOLS + j] += sum;
    }
}

// ---------------- launch ----------------
extern "C" void kernel_launch(void* const* d_in, const int* in_sizes, int n_in,
                              void* d_out, int out_size)
{
    const float* hidden = (const float*)d_in[0];
    const void*  ids    = d_in[1];
    const float* W1     = (const float*)d_in[2];
    const float* b1     = (const float*)d_in[3];
    const float* W2     = (const float*)d_in[4];
    const float* b2     = (const float*)d_in[5];
    const int*   n_ptr  = (const int*)d_in[6];
    float*       out    = (float*)d_out;

    detect_kernel<<<1, 1024>>>((const unsigned int*)ids);
    prep_codes_kernel<<<(MROWS + 255) / 256, 256>>>(ids, n_ptr);
    pool_kernel<<<MROWS, 256>>>(hidden);
    dim3 ggrid(NCOLS / BN, MROWS / BM);   // (8, 64)
    gemm_bias_kernel<<<ggrid, 256>>>(hidden, W1, b1, b2, out);
    fixup_kernel<<<MROWS, 256>>>(W2, out);
}

// round 4
// speedup vs baseline: 1.5479x; 1.5479x over previous
#include <cuda_runtime.h>
#include <cuda_bf16.h>
#include <cstdint>

// out [4,2048,1024] f32 = X@W1^T + b1 + pooled@W2^T + b2
// Main GEMM: warp-level mma.sync bf16 (sm_100-safe; tcgen05 needs sm_100a which
// the harness does NOT compile for) with split-bf16 hi/lo 3-MMA fp32 emulation.

static constexpr int BATCH = 4;
static constexpr int LSEQ  = 2048;
static constexpr int DDIM  = 1024;
static constexpr int MROWS = BATCH * LSEQ;   // 8192
static constexpr int NCOLS = DDIM;
static constexpr int KDIM  = DDIM;

// ---------------- device scratch (no dynamic allocations allowed) ----------------
__device__ unsigned long long g_codes[MROWS];
__device__ float g_pooled[(size_t)MROWS * DDIM];
__device__ int g_wl[MROWS];
__device__ int g_wl_count;
__device__ int g_ids_is64;
__device__ __align__(256) __nv_bfloat16 g_Ahi[(size_t)MROWS * KDIM];
__device__ __align__(256) __nv_bfloat16 g_Alo[(size_t)MROWS * KDIM];
__device__ __align__(256) __nv_bfloat16 g_Bhi[(size_t)NCOLS * KDIM];
__device__ __align__(256) __nv_bfloat16 g_Blo[(size_t)NCOLS * KDIM];

// ====================== PTX helpers (all sm_80+ portable) ======================
__device__ __forceinline__ uint32_t smem_u32(const void* p) {
    uint32_t a;
    asm("{ .reg .u64 t; cvta.to.shared.u64 t, %1; cvt.u32.u64 %0, t; }" : "=r"(a) : "l"(p));
    return a;
}
__device__ __forceinline__ void cp16(uint32_t dst, const void* src) {
    asm volatile("cp.async.cg.shared.global [%0], [%1], 16;" :: "r"(dst), "l"(src));
}
#define CP_COMMIT() asm volatile("cp.async.commit_group;" ::: "memory")
#define CP_WAIT(n)  asm volatile("cp.async.wait_group %0;" :: "n"(n) : "memory")

__device__ __forceinline__ void ldsm_x4(uint32_t* r, uint32_t addr) {
    asm volatile("ldmatrix.sync.aligned.m8n8.x4.shared.b16 {%0,%1,%2,%3}, [%4];"
        : "=r"(r[0]), "=r"(r[1]), "=r"(r[2]), "=r"(r[3]) : "r"(addr));
}
__device__ __forceinline__ void ldsm_x2(uint32_t* r, uint32_t addr) {
    asm volatile("ldmatrix.sync.aligned.m8n8.x2.shared.b16 {%0,%1}, [%2];"
        : "=r"(r[0]), "=r"(r[1]) : "r"(addr));
}
__device__ __forceinline__ void mma_bf16(float* c, const uint32_t* a, const uint32_t* b) {
    asm volatile("mma.sync.aligned.m16n8k16.row.col.f32.bf16.bf16.f32 "
        "{%0,%1,%2,%3}, {%4,%5,%6,%7}, {%8,%9}, {%0,%1,%2,%3};"
        : "+f"(c[0]), "+f"(c[1]), "+f"(c[2]), "+f"(c[3])
        : "r"(a[0]), "r"(a[1]), "r"(a[2]), "r"(a[3]), "r"(b[0]), "r"(b[1]));
}

// ---------------- kernel 0: detect ids dtype + reset worklist ----------------
__global__ void detect_kernel(const unsigned int* __restrict__ w)
{
    __shared__ int s_any;
    if (threadIdx.x == 0) s_any = 0;
    __syncthreads();
    for (int i = 2 * threadIdx.x + 1; i < MROWS; i += 2 * blockDim.x)
        if (w[i] != 0u) s_any = 1;
    __syncthreads();
    if (threadIdx.x == 0) {
        g_ids_is64 = (s_any == 0) ? 1 : 0;
        g_wl_count = 0;
    }
}

// ---------------- kernel 1: pack n-gram codes ----------------
__global__ void prep_codes_kernel(const void* __restrict__ ids_raw,
                                  const int* __restrict__ n_ptr)
{
    int idx = blockIdx.x * blockDim.x + threadIdx.x;
    if (idx >= MROWS) return;
    int n = *n_ptr;
    int is64 = g_ids_is64;
    const int*       i32 = (const int*)ids_raw;
    const long long* i64 = (const long long*)ids_raw;
    int b = idx / LSEQ;
    int q = idx % LSEQ;
    unsigned long long code = 0ull;
    if (q >= n - 1) {
        for (int i = 0; i < n; i++) {
            int pos = b * LSEQ + (q - n + 1 + i);
            long long v = is64 ? i64[pos] : (long long)i32[pos];
            code = (code << 16) | (unsigned long long)(v & 0xFFFF);
        }
    }
    g_codes[idx] = code;
}

// ---------------- kernel 2: matches -> pooled rows + worklist ----------------
__global__ __launch_bounds__(256) void pool_kernel(const float* __restrict__ hidden)
{
    __shared__ int s_match[LSEQ];
    __shared__ int s_cnt;
    int blk = blockIdx.x;
    int tid = threadIdx.x;
    int b = blk / LSEQ;
    int q = blk % LSEQ;
    if (tid == 0) s_cnt = 0;
    __syncthreads();
    unsigned long long myc = g_codes[blk];
    for (int k = tid; k < q; k += 256) {
        if (g_codes[b * LSEQ + k] == myc) {
            int pos = atomicAdd(&s_cnt, 1);
            s_match[pos] = k;
        }
    }
    __syncthreads();
    int cnt = s_cnt;
    if (cnt == 0) return;
    if (tid == 0) {
        int wi = atomicAdd(&g_wl_count, 1);
        g_wl[wi] = blk;
    }
    int c = tid * 4;
    float4 acc = make_float4(0.f, 0.f, 0.f, 0.f);
    for (int m = 0; m < cnt; m++) {
        const float4 h = *(const float4*)&hidden[((size_t)b * LSEQ + s_match[m]) * DDIM + c];
        acc.x += h.x; acc.y += h.y; acc.z += h.z; acc.w += h.w;
    }
    float inv = 1.0f / (float)cnt;
    acc.x *= inv; acc.y *= inv; acc.z *= inv; acc.w *= inv;
    *(float4*)&g_pooled[(size_t)blk * DDIM + c] = acc;
}

// ---------------- kernel: fp32 -> bf16 hi/lo split ----------------
__global__ void convert_kernel(const float* __restrict__ src,
                               __nv_bfloat16* __restrict__ dhi,
                               __nv_bfloat16* __restrict__ dlo,
                               int count4)
{
    int i = blockIdx.x * blockDim.x + threadIdx.x;
    int stride = gridDim.x * blockDim.x;
    for (; i < count4; i += stride) {
        float4 v = ((const float4*)src)[i];
        __nv_bfloat16 h0 = __float2bfloat16_rn(v.x);
        __nv_bfloat16 h1 = __float2bfloat16_rn(v.y);
        __nv_bfloat16 h2 = __float2bfloat16_rn(v.z);
        __nv_bfloat16 h3 = __float2bfloat16_rn(v.w);
        __nv_bfloat16 l0 = __float2bfloat16_rn(v.x - __bfloat162float(h0));
        __nv_bfloat16 l1 = __float2bfloat16_rn(v.y - __bfloat162float(h1));
        __nv_bfloat16 l2 = __float2bfloat16_rn(v.z - __bfloat162float(h2));
        __nv_bfloat16 l3 = __float2bfloat16_rn(v.w - __bfloat162float(h3));
        ((__nv_bfloat162*)dhi)[2 * i + 0] = __nv_bfloat162(h0, h1);
        ((__nv_bfloat162*)dhi)[2 * i + 1] = __nv_bfloat162(h2, h3);
        ((__nv_bfloat162*)dlo)[2 * i + 0] = __nv_bfloat162(l0, l1);
        ((__nv_bfloat162*)dlo)[2 * i + 1] = __nv_bfloat162(l2, l3);
    }
}

// ---------------- kernel 3: HMMA split-bf16 GEMM  C = X@W1^T + b1 + b2 ----------------
// CTA tile 128x256, BK=64 (128B swizzled rows). 8 warps (2x4), warp tile 64x64.
// 2-stage cp.async double buffer. Per k16-step: hihi, lohi, hilo MMAs.
static constexpr int TBM = 128, TBN = 256, TBK = 64;
static constexpr int N_CHUNKS = KDIM / TBK;                      // 16
static constexpr int ST_AHI = 0, ST_ALO = 16384, ST_BHI = 32768, ST_BLO = 65536;
static constexpr int STAGE_BYTES = 98304;                        // 96KB
static constexpr int SMEM_DYN = 1024 + 2 * STAGE_BYTES;          // align slack + 192KB

__global__ __launch_bounds__(256, 1)
void gemm_mma_kernel(const float* __restrict__ b1,
                     const float* __restrict__ b2,
                     float* __restrict__ C)
{
    extern __shared__ char smem[];
    uint32_t sbase = (smem_u32(smem) + 1023u) & ~1023u;

    int tid  = threadIdx.x;
    int wid  = tid >> 5;
    int lane = tid & 31;
    int row0 = blockIdx.y * TBM;
    int col0 = blockIdx.x * TBN;

    int wm = wid >> 2;            // 0..1
    int wn = wid & 3;             // 0..3
    int mbase = wm * 64;
    int nbase = wn * 64;

    // ---- per-thread ldmatrix address components ----
    // A: lanes 0-15 -> rows (lane&15), lanes 16-31 -> k+16B
    int arow_l = (lane & 15);
    int aklane = (lane >> 4) * 16;
    uint32_t aoffs[4], axors[4];
#pragma unroll
    for (int i = 0; i < 4; i++) {
        int r = mbase + 16 * i + arow_l;
        aoffs[i] = (uint32_t)(r * 128);
        axors[i] = (uint32_t)((r & 7) << 4);
    }
    // B: lanes 0-7 -> rows (lane&7) @k, lanes 8-15 -> @k+16B
    int brow_l = (lane & 7);
    int bklane = ((lane >> 3) & 1) * 16;
    uint32_t bxor = (uint32_t)(brow_l << 4);
    uint32_t boffs[8];
#pragma unroll
    for (int j = 0; j < 8; j++)
        boffs[j] = (uint32_t)((nbase + 8 * j + brow_l) * 128);

    float acc[4][8][4];
#pragma unroll
    for (int i = 0; i < 4; i++)
#pragma unroll
        for (int j = 0; j < 8; j++)
#pragma unroll
            for (int t = 0; t < 4; t++) acc[i][j][t] = 0.f;

    // ---- stage loader ----
    auto load_chunk = [&](int c, uint32_t sb) {
        int k0 = c * TBK;
        for (int i = tid; i < 1024; i += 256) {        // A: 128 rows x 8 chunks
            int r = i >> 3, c16 = i & 7;
            uint32_t off = (uint32_t)(r * 128 + c16 * 16);
            off ^= (uint32_t)((r & 7) << 4);
            size_t src = (size_t)(row0 + r) * KDIM + k0 + c16 * 8;
            cp16(sb + ST_AHI + off, &g_Ahi[src]);
            cp16(sb + ST_ALO + off, &g_Alo[src]);
        }
        for (int i = tid; i < 2048; i += 256) {        // B: 256 rows x 8 chunks
            int r = i >> 3, c16 = i & 7;
            uint32_t off = (uint32_t)(r * 128 + c16 * 16);
            off ^= (uint32_t)((r & 7) << 4);
            size_t src = (size_t)(col0 + r) * KDIM + k0 + c16 * 8;
            cp16(sb + ST_BHI + off, &g_Bhi[src]);
            cp16(sb + ST_BLO + off, &g_Blo[src]);
        }
        CP_COMMIT();
    };

    load_chunk(0, sbase);

    for (int c = 0; c < N_CHUNKS; c++) {
        uint32_t sb = sbase + (uint32_t)(c & 1) * STAGE_BYTES;
        if (c + 1 < N_CHUNKS) {
            load_chunk(c + 1, sbase + (uint32_t)((c + 1) & 1) * STAGE_BYTES);
            CP_WAIT(1);
        } else {
            CP_WAIT(0);
        }
        __syncthreads();

#pragma unroll
        for (int ks = 0; ks < 4; ks++) {
            uint32_t kb = (uint32_t)(ks * 32);
            uint32_t ahi[4][4], alo[4][4], bhi[8][2], blo[8][2];
            uint32_t akcol = (kb + aklane);
            uint32_t bkcol = (kb + bklane);
#pragma unroll
            for (int i = 0; i < 4; i++)
                ldsm_x4(ahi[i], sb + ST_AHI + aoffs[i] + (akcol ^ axors[i]));
#pragma unroll
            for (int j = 0; j < 8; j++)
                ldsm_x2(bhi[j], sb + ST_BHI + boffs[j] + (bkcol ^ bxor));
#pragma unroll
            for (int i = 0; i < 4; i++)
#pragma unroll
                for (int j = 0; j < 8; j++)
                    mma_bf16(acc[i][j], ahi[i], bhi[j]);
#pragma unroll
            for (int i = 0; i < 4; i++)
                ldsm_x4(alo[i], sb + ST_ALO + aoffs[i] + (akcol ^ axors[i]));
#pragma unroll
            for (int i = 0; i < 4; i++)
#pragma unroll
                for (int j = 0; j < 8; j++)
                    mma_bf16(acc[i][j], alo[i], bhi[j]);
#pragma unroll
            for (int j = 0; j < 8; j++)
                ldsm_x2(blo[j], sb + ST_BLO + boffs[j] + (bkcol ^ bxor));
#pragma unroll
            for (int i = 0; i < 4; i++)
#pragma unroll
                for (int j = 0; j < 8; j++)
                    mma_bf16(acc[i][j], ahi[i], blo[j]);
        }
        __syncthreads();   // stage consumed; safe to refill two iterations later
    }

    // ---- epilogue: fused bias, direct register -> gmem ----
    int quad = lane >> 2;
    int tq   = lane & 3;
#pragma unroll
    for (int j = 0; j < 8; j++) {
        int col = col0 + nbase + 8 * j + tq * 2;
        float2 s1 = *(const float2*)&b1[col];
        float2 s2 = *(const float2*)&b2[col];
        float bx = s1.x + s2.x, by = s1.y + s2.y;
#pragma unroll
        for (int i = 0; i < 4; i++) {
            int r0 = row0 + mbase + 16 * i + quad;
            float2 o0 = make_float2(acc[i][j][0] + bx, acc[i][j][1] + by);
            float2 o1 = make_float2(acc[i][j][2] + bx, acc[i][j][3] + by);
            *(float2*)&C[(size_t)r0 * NCOLS + col] = o0;
            *(float2*)&C[(size_t)(r0 + 8) * NCOLS + col] = o1;
        }
    }
}

// ---------------- kernel 4: sparse fixup  out[row] += pooled[row] @ W2^T ----------------
__global__ __launch_bounds__(256) void fixup_kernel(const float* __restrict__ W2,
                                                    float* __restrict__ C)
{
    int slot = blockIdx.x;
    if (slot >= g_wl_count) return;
    int row = g_wl[slot];

    __shared__ float s_x[DDIM];
    int tid = threadIdx.x;
    for (int d = tid; d < DDIM; d += 256) s_x[d] = g_pooled[(size_t)row * DDIM + d];
    __syncthreads();

    int warp = tid / 32;
    int lane = tid % 32;
    for (int j = warp * 128; j < warp * 128 + 128; j++) {
        const float* wrow = &W2[(size_t)j * KDIM];
        float sum = 0.f;
        for (int d = lane; d < KDIM; d += 32) sum += s_x[d] * wrow[d];
#pragma unroll
        for (int off = 16; off > 0; off >>= 1)
            sum += __shfl_down_sync(0xFFFFFFFFu, sum, off);
        if (lane == 0) C[(size_t)row * NCOLS + j] += sum;
    }
}

// ---------------- launch ----------------
extern "C" void kernel_launch(void* const* d_in, const int* in_sizes, int n_in,
                              void* d_out, int out_size)
{
    const float* hidden = (const float*)d_in[0];
    const void*  ids    = d_in[1];
    const float* W1     = (const float*)d_in[2];
    const float* b1     = (const float*)d_in[3];
    const float* W2     = (const float*)d_in[4];
    const float* b2     = (const float*)d_in[5];
    const int*   n_ptr  = (const int*)d_in[6];
    float*       out    = (float*)d_out;

    static bool attr_done = false;
    if (!attr_done) {
        cudaFuncSetAttribute(gemm_mma_kernel,
                             cudaFuncAttributeMaxDynamicSharedMemorySize, SMEM_DYN);
        attr_done = true;
    }

    void *pAhi, *pAlo, *pBhi, *pBlo;
    cudaGetSymbolAddress(&pAhi, g_Ahi);
    cudaGetSymbolAddress(&pAlo, g_Alo);
    cudaGetSymbolAddress(&pBhi, g_Bhi);
    cudaGetSymbolAddress(&pBlo, g_Blo);

    detect_kernel<<<1, 1024>>>((const unsigned int*)ids);
    prep_codes_kernel<<<(MROWS + 255) / 256, 256>>>(ids, n_ptr);
    convert_kernel<<<2048, 256>>>(hidden, (__nv_bfloat16*)pAhi, (__nv_bfloat16*)pAlo,
                                  MROWS * KDIM / 4);
    convert_kernel<<<512, 256>>>(W1, (__nv_bfloat16*)pBhi, (__nv_bfloat16*)pBlo,
                                 NCOLS * KDIM / 4);
    pool_kernel<<<MROWS, 256>>>(hidden);
    dim3 ggrid(NCOLS / TBN, MROWS / TBM);   // (4, 64)
    gemm_mma_kernel<<<ggrid, 256, SMEM_DYN>>>(b1, b2, out);
    fixup_kernel<<<MROWS, 256>>>(W2, out);
}